// round 10
// baseline (speedup 1.0000x reference)
#include <cuda_runtime.h>

// Bidirectional GRU, round 7: split architecture.
// Kernel A: gi[dir][t][3H][B] = x(t) @ Wih^T  (throughput GEMM, 2048 blocks)
// Kernel B: persistent recurrence, per step only h @ Whh^T + gates.
// Mapping (both): 256 thr = 2 jp-warps (4 j each) x 4 k-split warps;
// lane bg handles batches (bg, bg+32). Packed fma.rn.f32x2.

#define T_STEPS 512
#define BATCH   64
#define HID     512
#define NBLK_B  128
#define THREADS 256
#define PADF    516              // floats per staged row (129 float4, conflict-free)

#define OUT_ROW   1024           // 2H
#define OUT_TSTR  (BATCH * OUT_ROW)

// gi scratch: [2][T][3H][B] floats = 402.7 MB
__device__ float g_gi[2ull * T_STEPS * 3 * HID * BATCH];

__device__ unsigned g_count = 0;
__device__ unsigned g_gen   = 0;

__device__ __forceinline__ float sigmoidf_(float x) {
    return 1.0f / (1.0f + __expf(-x));
}
__device__ __forceinline__ float tanhf_(float x) {
    float xc = fminf(fmaxf(x, -15.f), 15.f);
    float e  = __expf(2.f * xc);
    return (e - 1.f) / (e + 1.f);
}
__device__ __forceinline__ void fma2(unsigned long long& d,
                                     unsigned long long a,
                                     unsigned long long b) {
    asm volatile("fma.rn.f32x2 %0, %1, %2, %0;" : "+l"(d) : "l"(a), "l"(b));
}
__device__ __forceinline__ float2 unpk(unsigned long long v) {
    float2 r;
    asm("mov.b64 {%0,%1}, %2;" : "=f"(r.x), "=f"(r.y) : "l"(v));
    return r;
}

__device__ __forceinline__ void grid_barrier() {
    __syncthreads();
    if (threadIdx.x == 0) {
        volatile unsigned* vgen = &g_gen;
        unsigned gen = *vgen;
        unsigned ticket = atomicAdd(&g_count, 1u);
        if (ticket == NBLK_B - 1u) {
            atomicExch(&g_count, 0u);
            __threadfence();
            atomicAdd(&g_gen, 1u);   // release
        } else {
            while (*vgen == gen) { __nanosleep(32); }
        }
    }
    __syncthreads();
}

// shared smem plan (both kernels):
//   ws : 3*8*512 floats          (weight slices, 3 gates x 8 j-cols)
//   st : 64*PADF floats          (staged x or h rows)
//   red: 192*50 floats           (k-split partials)
#define WS_FLOATS  (3 * 8 * 512)
#define ST_FLOATS  (BATCH * PADF)
#define RED_FLOATS (192 * 50)
#define SMEM_BYTES ((WS_FLOATS + ST_FLOATS + RED_FLOATS) * 4)

// ---------------------------------------------------------------------------
// Kernel A: x-projection GEMM. grid = 2 dirs x 64 jblk x 16 tq = 2048 blocks.
// Each block: 8 j-cols x 3 gates, 32 timesteps, all 64 batches.
// ---------------------------------------------------------------------------
extern "C" __global__ void __launch_bounds__(THREADS, 1)
gru_xproj_kernel(const float* __restrict__ inp,
                 const float* __restrict__ Wih_f,
                 const float* __restrict__ Wih_b)
{
    extern __shared__ float smem[];
    float* ws  = smem;
    float* st  = smem + WS_FLOATS;
    float* red = st + ST_FLOATS;

    const int tid  = threadIdx.x;
    const int tq   = blockIdx.x & 15;
    const int jblk = (blockIdx.x >> 4) & 63;
    const int dir  = blockIdx.x >> 10;
    const int j0   = jblk * 8;

    const float* Wih = dir ? Wih_b : Wih_f;

    // weights: ws[(g*8+jj)*512 + k] = Wih[g*HID + j0+jj][k]
    for (int i = tid; i < 3072; i += THREADS) {           // float4s
        int row = i >> 7;          // 0..23
        int c4  = i & 127;
        int g   = row >> 3;
        int jj  = row & 7;
        ((float4*)ws)[row * 128 + c4] =
            ((const float4*)(Wih + ((size_t)(g * HID + j0 + jj) << 9)))[c4];
    }

    const int bg   = tid & 31;
    const int warp = tid >> 5;
    const int jp   = warp & 1;         // 0..1 -> 4 j each
    const int ks   = warp >> 1;        // 0..3 k-split
    const int kbeg = ks * 128;

    const float* wp[12];               // [g][jj]
    #pragma unroll
    for (int g = 0; g < 3; ++g)
        #pragma unroll
        for (int jj = 0; jj < 4; ++jj)
            wp[g * 4 + jj] = ws + ((g * 8 + jp * 4 + jj) << 9);

    __syncthreads();

    for (int s = 0; s < 32; ++s) {
        const int t = tq * 32 + s;
        // ---- stage x[t]: 64 rows x 512 floats ----
        const float* xg = inp + (size_t)t * (BATCH * 512);
        #pragma unroll 4
        for (int i = tid; i < 8192; i += THREADS) {       // float4s
            int row = i >> 7;
            int c4  = i & 127;
            float4 v = __ldg((const float4*)(xg + ((size_t)row << 9)) + c4);
            *(float4*)(st + row * PADF + c4 * 4) = v;
        }
        __syncthreads();

        unsigned long long acc[3][4][2];
        #pragma unroll
        for (int g = 0; g < 3; ++g)
            #pragma unroll
            for (int jj = 0; jj < 4; ++jj)
                { acc[g][jj][0] = 0ull; acc[g][jj][1] = 0ull; }

        const float* r0 = st + bg * PADF;
        const float* r1 = st + (bg + 32) * PADF;

        #pragma unroll 2
        for (int k = kbeg; k < kbeg + 128; k += 4) {
            const ulonglong2 xv0 = *(const ulonglong2*)(r0 + k);
            const ulonglong2 xv1 = *(const ulonglong2*)(r1 + k);
            #pragma unroll
            for (int g = 0; g < 3; ++g)
                #pragma unroll
                for (int jj = 0; jj < 4; ++jj) {
                    const ulonglong2 w = *(const ulonglong2*)(wp[g * 4 + jj] + k);
                    fma2(acc[g][jj][0], xv0.x, w.x);
                    fma2(acc[g][jj][0], xv0.y, w.y);
                    fma2(acc[g][jj][1], xv1.x, w.x);
                    fma2(acc[g][jj][1], xv1.y, w.y);
                }
        }
        __syncthreads();   // st reuse next s; also orders red below

        // ---- k-split reduction ----
        if (ks != 0) {
            float* rr = red + ((ks - 1) * 64 + jp * 32 + bg) * 50;
            #pragma unroll
            for (int g = 0; g < 3; ++g)
                #pragma unroll
                for (int jj = 0; jj < 4; ++jj)
                    #pragma unroll
                    for (int bb = 0; bb < 2; ++bb)
                        *(float2*)(rr + ((g * 4 + jj) * 2 + bb) * 2)
                            = unpk(acc[g][jj][bb]);
        }
        __syncthreads();

        if (ks == 0) {
            float* gbase = g_gi + ((size_t)dir * T_STEPS + t) * (3 * HID * BATCH);
            const float* p1 = red + (0 * 64 + jp * 32 + bg) * 50;
            const float* p2 = red + (1 * 64 + jp * 32 + bg) * 50;
            const float* p3 = red + (2 * 64 + jp * 32 + bg) * 50;
            #pragma unroll
            for (int g = 0; g < 3; ++g)
                #pragma unroll
                for (int jj = 0; jj < 4; ++jj)
                    #pragma unroll
                    for (int bb = 0; bb < 2; ++bb) {
                        const int n = ((g * 4 + jj) * 2 + bb) * 2;
                        float2 v = unpk(acc[g][jj][bb]);
                        float2 q1 = *(const float2*)(p1 + n);
                        float2 q2 = *(const float2*)(p2 + n);
                        float2 q3 = *(const float2*)(p3 + n);
                        float sum = v.x + v.y + q1.x + q1.y
                                  + q2.x + q2.y + q3.x + q3.y;
                        gbase[(size_t)(g * HID + j0 + jp * 4 + jj) * BATCH
                              + bg + bb * 32] = sum;
                    }
        }
        __syncthreads();   // red reuse next s
    }
}

// ---------------------------------------------------------------------------
// Kernel B: persistent recurrence. 128 blocks = 2 dirs x 64 jblk.
// ---------------------------------------------------------------------------
extern "C" __global__ void __launch_bounds__(THREADS, 1)
gru_recur_kernel(const float* __restrict__ h0f,  const float* __restrict__ h0b,
                 const float* __restrict__ Whh_f, const float* __restrict__ Whh_b,
                 const float* __restrict__ bih_f, const float* __restrict__ bhh_f,
                 const float* __restrict__ bih_b, const float* __restrict__ bhh_b,
                 float* __restrict__ out)
{
    extern __shared__ float smem[];
    float* ws  = smem;
    float* st  = smem + WS_FLOATS;          // staged h_prev
    float* red = st + ST_FLOATS;

    const int tid  = threadIdx.x;
    const int dir  = blockIdx.x >> 6;
    const int jblk = blockIdx.x & 63;
    const int j0   = jblk * 8;

    const float* Whh = dir ? Whh_b : Whh_f;
    const float* bih = dir ? bih_b : bih_f;
    const float* bhh = dir ? bhh_b : bhh_f;
    const float* h0  = dir ? h0b   : h0f;

    for (int i = tid; i < 3072; i += THREADS) {
        int row = i >> 7;
        int c4  = i & 127;
        int g   = row >> 3;
        int jj  = row & 7;
        ((float4*)ws)[row * 128 + c4] =
            ((const float4*)(Whh + ((size_t)(g * HID + j0 + jj) << 9)))[c4];
    }

    const int bg   = tid & 31;
    const int warp = tid >> 5;
    const int jp   = warp & 1;
    const int ks   = warp >> 1;
    const int kbeg = ks * 128;
    const int jA   = j0 + jp * 4;

    const float* wp[12];
    #pragma unroll
    for (int g = 0; g < 3; ++g)
        #pragma unroll
        for (int jj = 0; jj < 4; ++jj)
            wp[g * 4 + jj] = ws + ((g * 8 + jp * 4 + jj) << 9);

    // biases for 4 j-cols
    float bR[4], bZ[4], bIN[4], bHN[4];
    #pragma unroll
    for (int jj = 0; jj < 4; ++jj) {
        int j = jA + jj;
        bR[jj]  = bih[j]           + bhh[j];
        bZ[jj]  = bih[HID + j]     + bhh[HID + j];
        bIN[jj] = bih[2 * HID + j];
        bHN[jj] = bhh[2 * HID + j];
    }

    float* hT_out = out + (size_t)T_STEPS * OUT_TSTR + (size_t)dir * (BATCH * HID);
    const float* gdir = g_gi + (size_t)dir * T_STEPS * (3 * HID * BATCH);

    __syncthreads();

    for (int s = 0; s < T_STEPS; ++s) {
        const int t  = dir ? (T_STEPS - 1 - s) : s;
        const int tp = dir ? (t + 1) : (t - 1);

        const float* hg;
        int hstr;
        if (s == 0) { hg = h0;                                      hstr = HID; }
        else        { hg = out + (size_t)tp * OUT_TSTR + dir * HID; hstr = OUT_ROW; }

        // ---- stage h_prev: 64 rows x 512 floats ----
        #pragma unroll 4
        for (int i = tid; i < 8192; i += THREADS) {
            int row = i >> 7;
            int c4  = i & 127;
            float4 v = __ldg((const float4*)(hg + (size_t)row * hstr) + c4);
            *(float4*)(st + row * PADF + c4 * 4) = v;
        }
        __syncthreads();

        // capture h_prev at this thread's own j-cols (epilogue threads only)
        float hp[4][2];
        if (ks == 0) {
            #pragma unroll
            for (int jj = 0; jj < 4; ++jj) {
                hp[jj][0] = st[bg * PADF + jA + jj];
                hp[jj][1] = st[(bg + 32) * PADF + jA + jj];
            }
        }

        unsigned long long acc[3][4][2];
        #pragma unroll
        for (int g = 0; g < 3; ++g)
            #pragma unroll
            for (int jj = 0; jj < 4; ++jj)
                { acc[g][jj][0] = 0ull; acc[g][jj][1] = 0ull; }

        const float* r0 = st + bg * PADF;
        const float* r1 = st + (bg + 32) * PADF;

        #pragma unroll 2
        for (int k = kbeg; k < kbeg + 128; k += 4) {
            const ulonglong2 hv0 = *(const ulonglong2*)(r0 + k);
            const ulonglong2 hv1 = *(const ulonglong2*)(r1 + k);
            #pragma unroll
            for (int g = 0; g < 3; ++g)
                #pragma unroll
                for (int jj = 0; jj < 4; ++jj) {
                    const ulonglong2 w = *(const ulonglong2*)(wp[g * 4 + jj] + k);
                    fma2(acc[g][jj][0], hv0.x, w.x);
                    fma2(acc[g][jj][0], hv0.y, w.y);
                    fma2(acc[g][jj][1], hv1.x, w.x);
                    fma2(acc[g][jj][1], hv1.y, w.y);
                }
        }
        __syncthreads();

        if (ks != 0) {
            float* rr = red + ((ks - 1) * 64 + jp * 32 + bg) * 50;
            #pragma unroll
            for (int g = 0; g < 3; ++g)
                #pragma unroll
                for (int jj = 0; jj < 4; ++jj)
                    #pragma unroll
                    for (int bb = 0; bb < 2; ++bb)
                        *(float2*)(rr + ((g * 4 + jj) * 2 + bb) * 2)
                            = unpk(acc[g][jj][bb]);
        }
        __syncthreads();

        if (ks == 0) {
            const float* gbase = gdir + (size_t)t * (3 * HID * BATCH);
            const float* p1 = red + (0 * 64 + jp * 32 + bg) * 50;
            const float* p2 = red + (1 * 64 + jp * 32 + bg) * 50;
            const float* p3 = red + (2 * 64 + jp * 32 + bg) * 50;

            #pragma unroll
            for (int bb = 0; bb < 2; ++bb) {
                float hn[4];
                #pragma unroll
                for (int jj = 0; jj < 4; ++jj) {
                    float hsum[3];
                    #pragma unroll
                    for (int g = 0; g < 3; ++g) {
                        const int n = ((g * 4 + jj) * 2 + bb) * 2;
                        float2 v  = unpk(acc[g][jj][bb]);
                        float2 q1 = *(const float2*)(p1 + n);
                        float2 q2 = *(const float2*)(p2 + n);
                        float2 q3 = *(const float2*)(p3 + n);
                        hsum[g] = v.x + v.y + q1.x + q1.y
                                + q2.x + q2.y + q3.x + q3.y;
                    }
                    const int j = jA + jj;
                    const int b = bg + bb * 32;
                    const float giR = __ldg(gbase + (size_t)(0 * HID + j) * BATCH + b);
                    const float giZ = __ldg(gbase + (size_t)(1 * HID + j) * BATCH + b);
                    const float giN = __ldg(gbase + (size_t)(2 * HID + j) * BATCH + b);
                    const float r = sigmoidf_(giR + hsum[0] + bR[jj]);
                    const float z = sigmoidf_(giZ + hsum[1] + bZ[jj]);
                    const float nn = tanhf_(giN + bIN[jj] + r * (hsum[2] + bHN[jj]));
                    hn[jj] = (1.0f - z) * nn + z * hp[jj][bb];
                }
                const int b = bg + bb * 32;
                *(float4*)(out + (size_t)t * OUT_TSTR + (size_t)b * OUT_ROW
                               + dir * HID + jA)
                    = make_float4(hn[0], hn[1], hn[2], hn[3]);
                if (s == T_STEPS - 1)
                    *(float4*)(hT_out + (size_t)b * HID + jA)
                        = make_float4(hn[0], hn[1], hn[2], hn[3]);
            }
        }

        // publish h to L2 + invalidate L1, then grid barrier
        __threadfence();
        grid_barrier();
    }
}

extern "C" void kernel_launch(void* const* d_in, const int* in_sizes, int n_in,
                              void* d_out, int out_size)
{
    (void)in_sizes; (void)n_in; (void)out_size;
    const float* inp   = (const float*)d_in[0];
    const float* h0f   = (const float*)d_in[1];
    const float* h0b   = (const float*)d_in[2];
    const float* Wih_f = (const float*)d_in[3];
    const float* Whh_f = (const float*)d_in[4];
    const float* bih_f = (const float*)d_in[5];
    const float* bhh_f = (const float*)d_in[6];
    const float* Wih_b = (const float*)d_in[7];
    const float* Whh_b = (const float*)d_in[8];
    const float* bih_b = (const float*)d_in[9];
    const float* bhh_b = (const float*)d_in[10];
    float* out = (float*)d_out;

    static int configured = 0;
    if (!configured) {
        cudaFuncSetAttribute(gru_xproj_kernel,
                             cudaFuncAttributeMaxDynamicSharedMemorySize, SMEM_BYTES);
        cudaFuncSetAttribute(gru_recur_kernel,
                             cudaFuncAttributeMaxDynamicSharedMemorySize, SMEM_BYTES);
        configured = 1;
    }

    gru_xproj_kernel<<<2048, THREADS, SMEM_BYTES>>>(inp, Wih_f, Wih_b);
    gru_recur_kernel<<<NBLK_B, THREADS, SMEM_BYTES>>>(
        h0f, h0b, Whh_f, Whh_b,
        bih_f, bhh_f, bih_b, bhh_b, out);
}

// round 16
// speedup vs baseline: 1.4574x; 1.4574x over previous
#include <cuda_runtime.h>

// Bidirectional GRU, round 16: R11 design with staging-loop fix.
// Kernel A: gi[dir][t][3H][B] = x(t) @ Wih^T  (2048 blocks, 2 blocks/SM)
// Kernel B: persistent recurrence, h @ Whh^T + gates, per-direction
//           single-thread release/acquire barrier (fan-in 64).

#define T_STEPS 512
#define BATCH   64
#define HID     512
#define NBLK_B  128
#define THREADS 256
#define PADF    516              // recur staged row: 129 float4, conflict-free
#define XCH     64               // xproj k-chunk
#define XPAD    68               // 64+4 floats, conflict-free

#define OUT_ROW   1024           // 2H
#define OUT_TSTR  (BATCH * OUT_ROW)

// gi scratch: [2][T][3H][B] floats = 402.7 MB
__device__ float g_gi[2ull * T_STEPS * 3 * HID * BATCH];

// per-direction barrier state, 128B apart
__device__ unsigned g_cnt[64];
__device__ unsigned g_gen2[64];

__device__ __forceinline__ float sigmoidf_(float x) {
    return 1.0f / (1.0f + __expf(-x));
}
__device__ __forceinline__ float tanhf_(float x) {
    float xc = fminf(fmaxf(x, -15.f), 15.f);
    float e  = __expf(2.f * xc);
    return (e - 1.f) / (e + 1.f);
}
__device__ __forceinline__ void fma2(unsigned long long& d,
                                     unsigned long long a,
                                     unsigned long long b) {
    asm volatile("fma.rn.f32x2 %0, %1, %2, %0;" : "+l"(d) : "l"(a), "l"(b));
}
__device__ __forceinline__ float2 unpk(unsigned long long v) {
    float2 r;
    asm("mov.b64 {%0,%1}, %2;" : "=f"(r.x), "=f"(r.y) : "l"(v));
    return r;
}
__device__ __forceinline__ unsigned ld_acq(const unsigned* p) {
    unsigned v;
    asm volatile("ld.acquire.gpu.u32 %0, [%1];" : "=r"(v) : "l"(p) : "memory");
    return v;
}

// Fast per-direction grid barrier. Only tid 0 fences: bar.sync orders the
// block's stores before tid0's cumulative fence.gpu (release); waiter side
// acquires gen then bar.sync orders the block's subsequent loads.
__device__ __forceinline__ void dir_barrier(int dir) {
    __syncthreads();
    if (threadIdx.x == 0) {
        unsigned* cnt = &g_cnt[dir * 32];
        unsigned* gen = &g_gen2[dir * 32];
        __threadfence();                       // release block's writes
        unsigned g = ld_acq(gen);              // current generation
        unsigned ticket = atomicAdd(cnt, 1u);
        if (ticket == 63u) {
            atomicExch(cnt, 0u);
            __threadfence();
            atomicAdd(gen, 1u);                // release
        } else {
            while (ld_acq(gen) == g) { __nanosleep(20); }
        }
    }
    __syncthreads();
}

// smem plans
#define WS_FLOATS   (3 * 8 * 512)                    // 12288
#define RED_FLOATS  (192 * 50)                       // 9600
#define SMEM_RECUR  ((WS_FLOATS + BATCH * PADF + RED_FLOATS) * 4)
#define SMEM_XPROJ  ((WS_FLOATS + BATCH * XPAD + RED_FLOATS) * 4)

// ---------------------------------------------------------------------------
// Kernel A: x-projection GEMM. grid = 2 dirs x 64 jblk x 16 tq = 2048 blocks.
// ---------------------------------------------------------------------------
extern "C" __global__ void __launch_bounds__(THREADS, 2)
gru_xproj_kernel(const float* __restrict__ inp,
                 const float* __restrict__ Wih_f,
                 const float* __restrict__ Wih_b)
{
    extern __shared__ float smem[];
    float* ws  = smem;
    float* st  = smem + WS_FLOATS;
    float* red = st + BATCH * XPAD;

    const int tid  = threadIdx.x;
    const int tq   = blockIdx.x & 15;
    const int jblk = (blockIdx.x >> 4) & 63;
    const int dir  = blockIdx.x >> 10;
    const int j0   = jblk * 8;

    const float* Wih = dir ? Wih_b : Wih_f;

    for (int i = tid; i < 3072; i += THREADS) {           // float4s
        int row = i >> 7;          // 0..23
        int c4  = i & 127;
        int g   = row >> 3;
        int jj  = row & 7;
        ((float4*)ws)[row * 128 + c4] =
            ((const float4*)(Wih + ((size_t)(g * HID + j0 + jj) << 9)))[c4];
    }

    const int bg   = tid & 31;
    const int warp = tid >> 5;
    const int jp   = warp & 1;         // 0..1 -> 4 j each
    const int ks   = warp >> 1;        // 0..3 k-split (16k per chunk)

    const float* wp[12];               // [g][jj]
    #pragma unroll
    for (int g = 0; g < 3; ++g)
        #pragma unroll
        for (int jj = 0; jj < 4; ++jj)
            wp[g * 4 + jj] = ws + ((g * 8 + jp * 4 + jj) << 9);

    __syncthreads();

    for (int s = 0; s < 32; ++s) {
        const int t = tq * 32 + s;
        const float* xg0 = inp + (size_t)t * (BATCH * 512);

        unsigned long long acc[3][4][2];
        #pragma unroll
        for (int g = 0; g < 3; ++g)
            #pragma unroll
            for (int jj = 0; jj < 4; ++jj)
                { acc[g][jj][0] = 0ull; acc[g][jj][1] = 0ull; }

        for (int c = 0; c < 8; ++c) {
            // stage chunk: 64 rows x 64 floats = 1024 float4s
            const float* xg = xg0 + c * XCH;
            #pragma unroll
            for (int i = 0; i < 4; ++i) {
                int idx = tid + i * THREADS;   // 0..1023
                int row = idx >> 4;            // 0..63
                int c4  = idx & 15;            // 0..15
                float4 v = __ldcg((const float4*)(xg + ((size_t)row << 9)) + c4);
                *(float4*)(st + row * XPAD + c4 * 4) = v;
            }
            __syncthreads();

            const float* r0 = st + bg * XPAD;
            const float* r1 = st + (bg + 32) * XPAD;
            const int kg = c * XCH;

            #pragma unroll
            for (int kk = ks * 16; kk < ks * 16 + 16; kk += 4) {
                const ulonglong2 xv0 = *(const ulonglong2*)(r0 + kk);
                const ulonglong2 xv1 = *(const ulonglong2*)(r1 + kk);
                const int k = kg + kk;
                #pragma unroll
                for (int g = 0; g < 3; ++g)
                    #pragma unroll
                    for (int jj = 0; jj < 4; ++jj) {
                        const ulonglong2 w = *(const ulonglong2*)(wp[g * 4 + jj] + k);
                        fma2(acc[g][jj][0], xv0.x, w.x);
                        fma2(acc[g][jj][0], xv0.y, w.y);
                        fma2(acc[g][jj][1], xv1.x, w.x);
                        fma2(acc[g][jj][1], xv1.y, w.y);
                    }
            }
            __syncthreads();   // before next chunk overwrites st
        }

        if (ks != 0) {
            float* rr = red + ((ks - 1) * 64 + jp * 32 + bg) * 50;
            #pragma unroll
            for (int g = 0; g < 3; ++g)
                #pragma unroll
                for (int jj = 0; jj < 4; ++jj)
                    #pragma unroll
                    for (int bb = 0; bb < 2; ++bb)
                        *(float2*)(rr + ((g * 4 + jj) * 2 + bb) * 2)
                            = unpk(acc[g][jj][bb]);
        }
        __syncthreads();

        if (ks == 0) {
            float* gbase = g_gi + ((size_t)dir * T_STEPS + t) * (3 * HID * BATCH);
            const float* p1 = red + (0 * 64 + jp * 32 + bg) * 50;
            const float* p2 = red + (1 * 64 + jp * 32 + bg) * 50;
            const float* p3 = red + (2 * 64 + jp * 32 + bg) * 50;
            #pragma unroll
            for (int g = 0; g < 3; ++g)
                #pragma unroll
                for (int jj = 0; jj < 4; ++jj)
                    #pragma unroll
                    for (int bb = 0; bb < 2; ++bb) {
                        const int n = ((g * 4 + jj) * 2 + bb) * 2;
                        float2 v  = unpk(acc[g][jj][bb]);
                        float2 q1 = *(const float2*)(p1 + n);
                        float2 q2 = *(const float2*)(p2 + n);
                        float2 q3 = *(const float2*)(p3 + n);
                        gbase[(size_t)(g * HID + j0 + jp * 4 + jj) * BATCH
                              + bg + bb * 32]
                            = v.x + v.y + q1.x + q1.y + q2.x + q2.y + q3.x + q3.y;
                    }
        }
        __syncthreads();   // red reuse next s
    }
}

// ---------------------------------------------------------------------------
// Kernel B: persistent recurrence. 128 blocks = 2 dirs x 64 jblk.
// ---------------------------------------------------------------------------
extern "C" __global__ void __launch_bounds__(THREADS, 1)
gru_recur_kernel(const float* __restrict__ h0f,  const float* __restrict__ h0b,
                 const float* __restrict__ Whh_f, const float* __restrict__ Whh_b,
                 const float* __restrict__ bih_f, const float* __restrict__ bhh_f,
                 const float* __restrict__ bih_b, const float* __restrict__ bhh_b,
                 float* __restrict__ out)
{
    extern __shared__ float smem[];
    float* ws  = smem;
    float* st  = smem + WS_FLOATS;          // staged h_prev [64][PADF]
    float* red = st + BATCH * PADF;

    const int tid  = threadIdx.x;
    const int dir  = blockIdx.x >> 6;
    const int jblk = blockIdx.x & 63;
    const int j0   = jblk * 8;

    const float* Whh = dir ? Whh_b : Whh_f;
    const float* bih = dir ? bih_b : bih_f;
    const float* bhh = dir ? bhh_b : bhh_f;
    const float* h0  = dir ? h0b   : h0f;

    for (int i = tid; i < 3072; i += THREADS) {
        int row = i >> 7;
        int c4  = i & 127;
        int g   = row >> 3;
        int jj  = row & 7;
        ((float4*)ws)[row * 128 + c4] =
            ((const float4*)(Whh + ((size_t)(g * HID + j0 + jj) << 9)))[c4];
    }

    const int bg   = tid & 31;
    const int warp = tid >> 5;
    const int jp   = warp & 1;
    const int ks   = warp >> 1;
    const int kbeg = ks * 128;
    const int jA   = j0 + jp * 4;

    const float* wp[12];
    #pragma unroll
    for (int g = 0; g < 3; ++g)
        #pragma unroll
        for (int jj = 0; jj < 4; ++jj)
            wp[g * 4 + jj] = ws + ((g * 8 + jp * 4 + jj) << 9);

    float bR[4], bZ[4], bIN[4], bHN[4];
    #pragma unroll
    for (int jj = 0; jj < 4; ++jj) {
        int j = jA + jj;
        bR[jj]  = bih[j]           + bhh[j];
        bZ[jj]  = bih[HID + j]     + bhh[HID + j];
        bIN[jj] = bih[2 * HID + j];
        bHN[jj] = bhh[2 * HID + j];
    }

    float* hT_out = out + (size_t)T_STEPS * OUT_TSTR + (size_t)dir * (BATCH * HID);
    const float* gdir = g_gi + (size_t)dir * T_STEPS * (3 * HID * BATCH);

    __syncthreads();

    for (int s = 0; s < T_STEPS; ++s) {
        const int t  = dir ? (T_STEPS - 1 - s) : s;
        const int tp = dir ? (t + 1) : (t - 1);

        const float* hg;
        int hstr;
        if (s == 0) { hg = h0;                                      hstr = HID; }
        else        { hg = out + (size_t)tp * OUT_TSTR + dir * HID; hstr = OUT_ROW; }

        // ---- prefetch gi for this t (epilogue warps only) ----
        float gi[3][4][2];
        if (ks == 0) {
            const float* gbase = gdir + (size_t)t * (3 * HID * BATCH);
            #pragma unroll
            for (int g = 0; g < 3; ++g)
                #pragma unroll
                for (int jj = 0; jj < 4; ++jj)
                    #pragma unroll
                    for (int bb = 0; bb < 2; ++bb)
                        gi[g][jj][bb] = __ldg(gbase
                            + (size_t)(g * HID + jA + jj) * BATCH + bg + bb * 32);
        }

        // ---- stage FULL h_prev: 64 rows x 512 floats = 8192 float4s ----
        // (R11 bug: staged only 2048 float4s -> 3/4 of st was garbage)
        #pragma unroll
        for (int i = 0; i < 32; ++i) {
            int idx = tid + i * THREADS;      // 0..8191
            int row = idx >> 7;               // 0..63
            int c4  = idx & 127;              // 0..127 float4s (512 floats)
            float4 v = __ldcg((const float4*)(hg + (size_t)row * hstr) + c4);
            *(float4*)(st + row * PADF + c4 * 4) = v;
        }
        __syncthreads();

        float hp[4][2];
        if (ks == 0) {
            #pragma unroll
            for (int jj = 0; jj < 4; ++jj) {
                hp[jj][0] = st[bg * PADF + jA + jj];
                hp[jj][1] = st[(bg + 32) * PADF + jA + jj];
            }
        }

        unsigned long long acc[3][4][2];
        #pragma unroll
        for (int g = 0; g < 3; ++g)
            #pragma unroll
            for (int jj = 0; jj < 4; ++jj)
                { acc[g][jj][0] = 0ull; acc[g][jj][1] = 0ull; }

        const float* r0 = st + bg * PADF;
        const float* r1 = st + (bg + 32) * PADF;

        #pragma unroll 2
        for (int k = kbeg; k < kbeg + 128; k += 4) {
            const ulonglong2 hv0 = *(const ulonglong2*)(r0 + k);
            const ulonglong2 hv1 = *(const ulonglong2*)(r1 + k);
            #pragma unroll
            for (int g = 0; g < 3; ++g)
                #pragma unroll
                for (int jj = 0; jj < 4; ++jj) {
                    const ulonglong2 w = *(const ulonglong2*)(wp[g * 4 + jj] + k);
                    fma2(acc[g][jj][0], hv0.x, w.x);
                    fma2(acc[g][jj][0], hv0.y, w.y);
                    fma2(acc[g][jj][1], hv1.x, w.x);
                    fma2(acc[g][jj][1], hv1.y, w.y);
                }
        }
        __syncthreads();

        if (ks != 0) {
            float* rr = red + ((ks - 1) * 64 + jp * 32 + bg) * 50;
            #pragma unroll
            for (int g = 0; g < 3; ++g)
                #pragma unroll
                for (int jj = 0; jj < 4; ++jj)
                    #pragma unroll
                    for (int bb = 0; bb < 2; ++bb)
                        *(float2*)(rr + ((g * 4 + jj) * 2 + bb) * 2)
                            = unpk(acc[g][jj][bb]);
        }
        __syncthreads();

        if (ks == 0) {
            const float* p1 = red + (0 * 64 + jp * 32 + bg) * 50;
            const float* p2 = red + (1 * 64 + jp * 32 + bg) * 50;
            const float* p3 = red + (2 * 64 + jp * 32 + bg) * 50;

            #pragma unroll
            for (int bb = 0; bb < 2; ++bb) {
                float hn[4];
                #pragma unroll
                for (int jj = 0; jj < 4; ++jj) {
                    float hsum[3];
                    #pragma unroll
                    for (int g = 0; g < 3; ++g) {
                        const int n = ((g * 4 + jj) * 2 + bb) * 2;
                        float2 v  = unpk(acc[g][jj][bb]);
                        float2 q1 = *(const float2*)(p1 + n);
                        float2 q2 = *(const float2*)(p2 + n);
                        float2 q3 = *(const float2*)(p3 + n);
                        hsum[g] = v.x + v.y + q1.x + q1.y
                                + q2.x + q2.y + q3.x + q3.y;
                    }
                    const float r = sigmoidf_(gi[0][jj][bb] + hsum[0] + bR[jj]);
                    const float z = sigmoidf_(gi[1][jj][bb] + hsum[1] + bZ[jj]);
                    const float nn = tanhf_(gi[2][jj][bb] + bIN[jj]
                                            + r * (hsum[2] + bHN[jj]));
                    hn[jj] = (1.0f - z) * nn + z * hp[jj][bb];
                }
                const int b = bg + bb * 32;
                *(float4*)(out + (size_t)t * OUT_TSTR + (size_t)b * OUT_ROW
                               + dir * HID + jA)
                    = make_float4(hn[0], hn[1], hn[2], hn[3]);
                if (s == T_STEPS - 1)
                    *(float4*)(hT_out + (size_t)b * HID + jA)
                        = make_float4(hn[0], hn[1], hn[2], hn[3]);
            }
        }

        dir_barrier(dir);
    }
}

extern "C" void kernel_launch(void* const* d_in, const int* in_sizes, int n_in,
                              void* d_out, int out_size)
{
    (void)in_sizes; (void)n_in; (void)out_size;
    const float* inp   = (const float*)d_in[0];
    const float* h0f   = (const float*)d_in[1];
    const float* h0b   = (const float*)d_in[2];
    const float* Wih_f = (const float*)d_in[3];
    const float* Whh_f = (const float*)d_in[4];
    const float* bih_f = (const float*)d_in[5];
    const float* bhh_f = (const float*)d_in[6];
    const float* Wih_b = (const float*)d_in[7];
    const float* Whh_b = (const float*)d_in[8];
    const float* bih_b = (const float*)d_in[9];
    const float* bhh_b = (const float*)d_in[10];
    float* out = (float*)d_out;

    static int configured = 0;
    if (!configured) {
        cudaFuncSetAttribute(gru_xproj_kernel,
                             cudaFuncAttributeMaxDynamicSharedMemorySize, SMEM_XPROJ);
        cudaFuncSetAttribute(gru_recur_kernel,
                             cudaFuncAttributeMaxDynamicSharedMemorySize, SMEM_RECUR);
        configured = 1;
    }

    gru_xproj_kernel<<<2048, THREADS, SMEM_XPROJ>>>(inp, Wih_f, Wih_b);
    gru_recur_kernel<<<NBLK_B, THREADS, SMEM_RECUR>>>(
        h0f, h0b, Whh_f, Whh_b,
        bih_f, bhh_f, bih_b, bhh_b, out);
}

// round 17
// speedup vs baseline: 1.5967x; 1.0956x over previous
#include <cuda_runtime.h>

// Bidirectional GRU, round 17: R16 + cp.async double-buffered pipelines.
// Kernel A: gi[dir][t][3H][B] = x(t) @ Wih^T  (2048 blocks)
// Kernel B: persistent recurrence, h @ Whh^T + gates, per-direction
//           single-thread release/acquire barrier (fan-in 64).

#define T_STEPS 512
#define BATCH   64
#define HID     512
#define NBLK_B  128
#define THREADS 256
#define CPAD    132              // recur chunk row: 128+4 floats, conflict-free
#define XPAD    68               // xproj chunk row: 64+4 floats, conflict-free

#define OUT_ROW   1024           // 2H
#define OUT_TSTR  (BATCH * OUT_ROW)

// gi scratch: [2][T][3H][B] floats = 402.7 MB
__device__ float g_gi[2ull * T_STEPS * 3 * HID * BATCH];

// per-direction barrier state, 128B apart
__device__ unsigned g_cnt[64];
__device__ unsigned g_gen2[64];

__device__ __forceinline__ float sigmoidf_(float x) {
    return 1.0f / (1.0f + __expf(-x));
}
__device__ __forceinline__ float tanhf_(float x) {
    float xc = fminf(fmaxf(x, -15.f), 15.f);
    float e  = __expf(2.f * xc);
    return (e - 1.f) / (e + 1.f);
}
__device__ __forceinline__ void fma2(unsigned long long& d,
                                     unsigned long long a,
                                     unsigned long long b) {
    asm volatile("fma.rn.f32x2 %0, %1, %2, %0;" : "+l"(d) : "l"(a), "l"(b));
}
__device__ __forceinline__ float2 unpk(unsigned long long v) {
    float2 r;
    asm("mov.b64 {%0,%1}, %2;" : "=f"(r.x), "=f"(r.y) : "l"(v));
    return r;
}
__device__ __forceinline__ unsigned ld_acq(const unsigned* p) {
    unsigned v;
    asm volatile("ld.acquire.gpu.u32 %0, [%1];" : "=r"(v) : "l"(p) : "memory");
    return v;
}
// async 16B copy global->shared, L1-bypass (L2-coherent with release fence)
__device__ __forceinline__ void cpa16(void* s, const void* g) {
    unsigned sa = (unsigned)__cvta_generic_to_shared(s);
    asm volatile("cp.async.cg.shared.global [%0], [%1], 16;" :: "r"(sa), "l"(g));
}
#define CPA_COMMIT() asm volatile("cp.async.commit_group;" ::: "memory")
#define CPA_WAIT(n)  asm volatile("cp.async.wait_group %0;" :: "n"(n) : "memory")

// Fast per-direction grid barrier; only tid 0 fences (cumulative release).
__device__ __forceinline__ void dir_barrier(int dir) {
    __syncthreads();
    if (threadIdx.x == 0) {
        unsigned* cnt = &g_cnt[dir * 32];
        unsigned* gen = &g_gen2[dir * 32];
        __threadfence();                       // release block's writes
        unsigned g = ld_acq(gen);
        unsigned ticket = atomicAdd(cnt, 1u);
        if (ticket == 63u) {
            atomicExch(cnt, 0u);
            __threadfence();
            atomicAdd(gen, 1u);                // release
        } else {
            while (ld_acq(gen) == g) { __nanosleep(20); }
        }
    }
    __syncthreads();
}

// smem plans
#define WS_FLOATS   (3 * 8 * 512)                    // 12288
#define RED_FLOATS  (192 * 50)                       // 9600
// recur: ws + 2 chunk buffers (64 x CPAD) + red = 155,136 B
#define SMEM_RECUR  ((WS_FLOATS + 2 * BATCH * CPAD + RED_FLOATS) * 4)
// xproj: ws + 2 chunk buffers (64 x XPAD) + red = 122,368 B
#define SMEM_XPROJ  ((WS_FLOATS + 2 * BATCH * XPAD + RED_FLOATS) * 4)

// ---------------------------------------------------------------------------
// Kernel A: x-projection GEMM. grid = 2 dirs x 64 jblk x 16 tq = 2048 blocks.
// cp.async double-buffered: 8 chunks of 64 cols per timestep.
// ---------------------------------------------------------------------------
extern "C" __global__ void __launch_bounds__(THREADS, 1)
gru_xproj_kernel(const float* __restrict__ inp,
                 const float* __restrict__ Wih_f,
                 const float* __restrict__ Wih_b)
{
    extern __shared__ float smem[];
    float* ws   = smem;
    float* buf0 = smem + WS_FLOATS;
    float* buf1 = buf0 + BATCH * XPAD;
    float* red  = buf1 + BATCH * XPAD;

    const int tid  = threadIdx.x;
    const int tq   = blockIdx.x & 15;
    const int jblk = (blockIdx.x >> 4) & 63;
    const int dir  = blockIdx.x >> 10;
    const int j0   = jblk * 8;

    const float* Wih = dir ? Wih_b : Wih_f;

    for (int i = tid; i < 3072; i += THREADS) {           // float4s
        int row = i >> 7;          // 0..23
        int c4  = i & 127;
        int g   = row >> 3;
        int jj  = row & 7;
        ((float4*)ws)[row * 128 + c4] =
            ((const float4*)(Wih + ((size_t)(g * HID + j0 + jj) << 9)))[c4];
    }

    const int bg   = tid & 31;
    const int warp = tid >> 5;
    const int jp   = warp & 1;         // 0..1 -> 4 j each
    const int ks   = warp >> 1;        // 0..3 -> 16-col stripe per chunk

    const float* wp[12];               // [g][jj]
    #pragma unroll
    for (int g = 0; g < 3; ++g)
        #pragma unroll
        for (int jj = 0; jj < 4; ++jj)
            wp[g * 4 + jj] = ws + ((g * 8 + jp * 4 + jj) << 9);

    // staging indices (4 float4s per thread per 64-col chunk)
    const int srow = tid >> 4 << 2;    // base row block per i: recompute inline

    __syncthreads();

    for (int s = 0; s < 32; ++s) {
        const int t = tq * 32 + s;
        const float* xg0 = inp + (size_t)t * (BATCH * 512);

        unsigned long long acc[3][4][2];
        #pragma unroll
        for (int g = 0; g < 3; ++g)
            #pragma unroll
            for (int jj = 0; jj < 4; ++jj)
                { acc[g][jj][0] = 0ull; acc[g][jj][1] = 0ull; }

        // prologue: stage chunk 0
        {
            float* b = buf0;
            #pragma unroll
            for (int i = 0; i < 4; ++i) {
                int idx = tid + i * THREADS;   // 0..1023
                int row = idx >> 4;
                int c4  = idx & 15;
                cpa16(b + row * XPAD + c4 * 4,
                      xg0 + (size_t)row * 512 + c4 * 4);
            }
            CPA_COMMIT();
        }

        #pragma unroll
        for (int c = 0; c < 8; ++c) {
            float* cur = (c & 1) ? buf1 : buf0;
            if (c < 7) {
                float* nxt = (c & 1) ? buf0 : buf1;
                const float* xg = xg0 + (c + 1) * 64;
                #pragma unroll
                for (int i = 0; i < 4; ++i) {
                    int idx = tid + i * THREADS;
                    int row = idx >> 4;
                    int c4  = idx & 15;
                    cpa16(nxt + row * XPAD + c4 * 4,
                          xg + (size_t)row * 512 + c4 * 4);
                }
                CPA_COMMIT();
                CPA_WAIT(1);
            } else {
                CPA_WAIT(0);
            }
            __syncthreads();

            const float* r0 = cur + bg * XPAD;
            const float* r1 = r0 + 32 * XPAD;
            const int kg = c * 64;

            #pragma unroll
            for (int kk = ks * 16; kk < ks * 16 + 16; kk += 4) {
                const ulonglong2 xv0 = *(const ulonglong2*)(r0 + kk);
                const ulonglong2 xv1 = *(const ulonglong2*)(r1 + kk);
                const int k = kg + kk;
                #pragma unroll
                for (int g = 0; g < 3; ++g)
                    #pragma unroll
                    for (int jj = 0; jj < 4; ++jj) {
                        const ulonglong2 w = *(const ulonglong2*)(wp[g * 4 + jj] + k);
                        fma2(acc[g][jj][0], xv0.x, w.x);
                        fma2(acc[g][jj][0], xv0.y, w.y);
                        fma2(acc[g][jj][1], xv1.x, w.x);
                        fma2(acc[g][jj][1], xv1.y, w.y);
                    }
            }
            __syncthreads();   // cur may be refilled at c+2
        }

        if (ks != 0) {
            float* rr = red + ((ks - 1) * 64 + jp * 32 + bg) * 50;
            #pragma unroll
            for (int g = 0; g < 3; ++g)
                #pragma unroll
                for (int jj = 0; jj < 4; ++jj)
                    #pragma unroll
                    for (int bb = 0; bb < 2; ++bb)
                        *(float2*)(rr + ((g * 4 + jj) * 2 + bb) * 2)
                            = unpk(acc[g][jj][bb]);
        }
        __syncthreads();

        if (ks == 0) {
            float* gbase = g_gi + ((size_t)dir * T_STEPS + t) * (3 * HID * BATCH);
            const float* p1 = red + (0 * 64 + jp * 32 + bg) * 50;
            const float* p2 = red + (1 * 64 + jp * 32 + bg) * 50;
            const float* p3 = red + (2 * 64 + jp * 32 + bg) * 50;
            #pragma unroll
            for (int g = 0; g < 3; ++g)
                #pragma unroll
                for (int jj = 0; jj < 4; ++jj)
                    #pragma unroll
                    for (int bb = 0; bb < 2; ++bb) {
                        const int n = ((g * 4 + jj) * 2 + bb) * 2;
                        float2 v  = unpk(acc[g][jj][bb]);
                        float2 q1 = *(const float2*)(p1 + n);
                        float2 q2 = *(const float2*)(p2 + n);
                        float2 q3 = *(const float2*)(p3 + n);
                        gbase[(size_t)(g * HID + j0 + jp * 4 + jj) * BATCH
                              + bg + bb * 32]
                            = v.x + v.y + q1.x + q1.y + q2.x + q2.y + q3.x + q3.y;
                    }
        }
        __syncthreads();   // red reuse next s
    }
    (void)srow;
}

// ---------------------------------------------------------------------------
// Kernel B: persistent recurrence. 128 blocks = 2 dirs x 64 jblk.
// cp.async double-buffered: 4 chunks of 128 cols per step.
// ---------------------------------------------------------------------------
extern "C" __global__ void __launch_bounds__(THREADS, 1)
gru_recur_kernel(const float* __restrict__ h0f,  const float* __restrict__ h0b,
                 const float* __restrict__ Whh_f, const float* __restrict__ Whh_b,
                 const float* __restrict__ bih_f, const float* __restrict__ bhh_f,
                 const float* __restrict__ bih_b, const float* __restrict__ bhh_b,
                 float* __restrict__ out)
{
    extern __shared__ float smem[];
    float* ws   = smem;
    float* buf0 = smem + WS_FLOATS;
    float* buf1 = buf0 + BATCH * CPAD;
    float* red  = buf1 + BATCH * CPAD;

    const int tid  = threadIdx.x;
    const int dir  = blockIdx.x >> 6;
    const int jblk = blockIdx.x & 63;
    const int j0   = jblk * 8;

    const float* Whh = dir ? Whh_b : Whh_f;
    const float* bih = dir ? bih_b : bih_f;
    const float* bhh = dir ? bhh_b : bhh_f;
    const float* h0  = dir ? h0b   : h0f;

    for (int i = tid; i < 3072; i += THREADS) {
        int row = i >> 7;
        int c4  = i & 127;
        int g   = row >> 3;
        int jj  = row & 7;
        ((float4*)ws)[row * 128 + c4] =
            ((const float4*)(Whh + ((size_t)(g * HID + j0 + jj) << 9)))[c4];
    }

    const int bg   = tid & 31;
    const int warp = tid >> 5;
    const int jp   = warp & 1;
    const int ks   = warp >> 1;        // 32-col stripe within each 128 chunk
    const int jA   = j0 + jp * 4;
    const int jchunk = j0 >> 7;        // chunk containing this block's j-cols
    const int j_in   = jA & 127;

    const float* wp[12];
    #pragma unroll
    for (int g = 0; g < 3; ++g)
        #pragma unroll
        for (int jj = 0; jj < 4; ++jj)
            wp[g * 4 + jj] = ws + ((g * 8 + jp * 4 + jj) << 9);

    float bR[4], bZ[4], bIN[4], bHN[4];
    #pragma unroll
    for (int jj = 0; jj < 4; ++jj) {
        int j = jA + jj;
        bR[jj]  = bih[j]           + bhh[j];
        bZ[jj]  = bih[HID + j]     + bhh[HID + j];
        bIN[jj] = bih[2 * HID + j];
        bHN[jj] = bhh[2 * HID + j];
    }

    float* hT_out = out + (size_t)T_STEPS * OUT_TSTR + (size_t)dir * (BATCH * HID);
    const float* gdir = g_gi + (size_t)dir * T_STEPS * (3 * HID * BATCH);

    __syncthreads();

    for (int s = 0; s < T_STEPS; ++s) {
        const int t  = dir ? (T_STEPS - 1 - s) : s;
        const int tp = dir ? (t + 1) : (t - 1);

        const float* hg;
        int hstr;
        if (s == 0) { hg = h0;                                      hstr = HID; }
        else        { hg = out + (size_t)tp * OUT_TSTR + dir * HID; hstr = OUT_ROW; }

        // prologue: stage chunk 0 (8 cp.async x 256 thr = 2048 float4)
        #pragma unroll
        for (int i = 0; i < 8; ++i) {
            int idx = tid + i * THREADS;      // 0..2047
            int row = idx >> 5;               // 0..63
            int c4  = idx & 31;               // 0..31
            cpa16(buf0 + row * CPAD + c4 * 4,
                  hg + (size_t)row * hstr + c4 * 4);
        }
        CPA_COMMIT();

        // gi prefetch overlaps with chunk-0 staging (epilogue warps only)
        float gi[3][4][2];
        if (ks == 0) {
            const float* gbase = gdir + (size_t)t * (3 * HID * BATCH);
            #pragma unroll
            for (int g = 0; g < 3; ++g)
                #pragma unroll
                for (int jj = 0; jj < 4; ++jj)
                    #pragma unroll
                    for (int bb = 0; bb < 2; ++bb)
                        gi[g][jj][bb] = __ldg(gbase
                            + (size_t)(g * HID + jA + jj) * BATCH + bg + bb * 32);
        }

        unsigned long long acc[3][4][2];
        #pragma unroll
        for (int g = 0; g < 3; ++g)
            #pragma unroll
            for (int jj = 0; jj < 4; ++jj)
                { acc[g][jj][0] = 0ull; acc[g][jj][1] = 0ull; }

        float hp[4][2];

        #pragma unroll
        for (int c = 0; c < 4; ++c) {
            float* cur = (c & 1) ? buf1 : buf0;
            if (c < 3) {
                float* nxt = (c & 1) ? buf0 : buf1;
                const float* hgc = hg + (c + 1) * 128;
                #pragma unroll
                for (int i = 0; i < 8; ++i) {
                    int idx = tid + i * THREADS;
                    int row = idx >> 5;
                    int c4  = idx & 31;
                    cpa16(nxt + row * CPAD + c4 * 4,
                          hgc + (size_t)row * hstr + c4 * 4);
                }
                CPA_COMMIT();
                CPA_WAIT(1);
            } else {
                CPA_WAIT(0);
            }
            __syncthreads();

            if (ks == 0 && c == jchunk) {
                #pragma unroll
                for (int jj = 0; jj < 4; ++jj) {
                    hp[jj][0] = cur[bg * CPAD + j_in + jj];
                    hp[jj][1] = cur[(bg + 32) * CPAD + j_in + jj];
                }
            }

            const float* r0 = cur + bg * CPAD;
            const float* r1 = r0 + 32 * CPAD;
            const int kg = c * 128;

            #pragma unroll
            for (int kk = ks * 32; kk < ks * 32 + 32; kk += 4) {
                const ulonglong2 hv0 = *(const ulonglong2*)(r0 + kk);
                const ulonglong2 hv1 = *(const ulonglong2*)(r1 + kk);
                const int k = kg + kk;
                #pragma unroll
                for (int g = 0; g < 3; ++g)
                    #pragma unroll
                    for (int jj = 0; jj < 4; ++jj) {
                        const ulonglong2 w = *(const ulonglong2*)(wp[g * 4 + jj] + k);
                        fma2(acc[g][jj][0], hv0.x, w.x);
                        fma2(acc[g][jj][0], hv0.y, w.y);
                        fma2(acc[g][jj][1], hv1.x, w.x);
                        fma2(acc[g][jj][1], hv1.y, w.y);
                    }
            }
            __syncthreads();   // cur may be refilled at c+2
        }

        if (ks != 0) {
            float* rr = red + ((ks - 1) * 64 + jp * 32 + bg) * 50;
            #pragma unroll
            for (int g = 0; g < 3; ++g)
                #pragma unroll
                for (int jj = 0; jj < 4; ++jj)
                    #pragma unroll
                    for (int bb = 0; bb < 2; ++bb)
                        *(float2*)(rr + ((g * 4 + jj) * 2 + bb) * 2)
                            = unpk(acc[g][jj][bb]);
        }
        __syncthreads();

        if (ks == 0) {
            const float* p1 = red + (0 * 64 + jp * 32 + bg) * 50;
            const float* p2 = red + (1 * 64 + jp * 32 + bg) * 50;
            const float* p3 = red + (2 * 64 + jp * 32 + bg) * 50;

            #pragma unroll
            for (int bb = 0; bb < 2; ++bb) {
                float hn[4];
                #pragma unroll
                for (int jj = 0; jj < 4; ++jj) {
                    float hsum[3];
                    #pragma unroll
                    for (int g = 0; g < 3; ++g) {
                        const int n = ((g * 4 + jj) * 2 + bb) * 2;
                        float2 v  = unpk(acc[g][jj][bb]);
                        float2 q1 = *(const float2*)(p1 + n);
                        float2 q2 = *(const float2*)(p2 + n);
                        float2 q3 = *(const float2*)(p3 + n);
                        hsum[g] = v.x + v.y + q1.x + q1.y
                                + q2.x + q2.y + q3.x + q3.y;
                    }
                    const float r = sigmoidf_(gi[0][jj][bb] + hsum[0] + bR[jj]);
                    const float z = sigmoidf_(gi[1][jj][bb] + hsum[1] + bZ[jj]);
                    const float nn = tanhf_(gi[2][jj][bb] + bIN[jj]
                                            + r * (hsum[2] + bHN[jj]));
                    hn[jj] = (1.0f - z) * nn + z * hp[jj][bb];
                }
                const int b = bg + bb * 32;
                *(float4*)(out + (size_t)t * OUT_TSTR + (size_t)b * OUT_ROW
                               + dir * HID + jA)
                    = make_float4(hn[0], hn[1], hn[2], hn[3]);
                if (s == T_STEPS - 1)
                    *(float4*)(hT_out + (size_t)b * HID + jA)
                        = make_float4(hn[0], hn[1], hn[2], hn[3]);
            }
        }

        dir_barrier(dir);
    }
}

extern "C" void kernel_launch(void* const* d_in, const int* in_sizes, int n_in,
                              void* d_out, int out_size)
{
    (void)in_sizes; (void)n_in; (void)out_size;
    const float* inp   = (const float*)d_in[0];
    const float* h0f   = (const float*)d_in[1];
    const float* h0b   = (const float*)d_in[2];
    const float* Wih_f = (const float*)d_in[3];
    const float* Whh_f = (const float*)d_in[4];
    const float* bih_f = (const float*)d_in[5];
    const float* bhh_f = (const float*)d_in[6];
    const float* Wih_b = (const float*)d_in[7];
    const float* Whh_b = (const float*)d_in[8];
    const float* bih_b = (const float*)d_in[9];
    const float* bhh_b = (const float*)d_in[10];
    float* out = (float*)d_out;

    static int configured = 0;
    if (!configured) {
        cudaFuncSetAttribute(gru_xproj_kernel,
                             cudaFuncAttributeMaxDynamicSharedMemorySize, SMEM_XPROJ);
        cudaFuncSetAttribute(gru_recur_kernel,
                             cudaFuncAttributeMaxDynamicSharedMemorySize, SMEM_RECUR);
        configured = 1;
    }

    gru_xproj_kernel<<<2048, THREADS, SMEM_XPROJ>>>(inp, Wih_f, Wih_b);
    gru_recur_kernel<<<NBLK_B, THREADS, SMEM_RECUR>>>(
        h0f, h0b, Whh_f, Whh_b,
        bih_f, bhh_f, bih_b, bhh_b, out);
}